// round 6
// baseline (speedup 1.0000x reference)
#include <cuda_runtime.h>
#include <math.h>
#include <stdint.h>

// ---------------------------------------------------------------------------
// Shapes (fixed by the problem)
// ---------------------------------------------------------------------------
#define LQ    1024      // sentence length
#define HIDQ  1024      // bidirectional hidden
#define HDIRQ 512       // per-direction hidden
#define DIN0  400       // WDIM + PDIM
#define MLPH  512       // MLP/2
#define G4H   2048      // 4 * HDIR

// Recurrence geometry: 128 CTAs (64/dir), 256 thr. CTA owns 8 h-elems
// (32 gate rows). Warp w <-> h-chunk [w*64, w*64+64); lane <-> gate row.
#define NCTA_DIR 64
#define JV       8

// ---------------------------------------------------------------------------
// Device scratch (no allocations allowed -> __device__ globals)
// ---------------------------------------------------------------------------
__device__ float g_emb[LQ * DIN0];
__device__ float g_xp[2 * LQ * G4H];
__device__ float g_hcat0[LQ * HIDQ];
__device__ float g_hcat1[LQ * HIDQ];
__device__ float g_featH[LQ * MLPH];
__device__ float g_featM[LQ * MLPH];
__device__ float g_shead[LQ];
__device__ float g_smodif[LQ];
__device__ int   g_flags[2 * NCTA_DIR];

__device__ __forceinline__ float fast_sigmoid(float x)
{
    return 1.f / (1.f + __expf(-x));
}
__device__ __forceinline__ float fast_tanh(float x)
{
    float e = __expf(-2.f * x);
    return (1.f - e) / (1.f + e);
}

// ---------------------------------------------------------------------------
// Embedding gather
// ---------------------------------------------------------------------------
__global__ void embed_kernel(const int* __restrict__ wt, const int* __restrict__ pt,
                             const float* __restrict__ we, const float* __restrict__ pe)
{
    int l = blockIdx.x;
    int w = wt[l];
    int p = pt[l];
    for (int k = threadIdx.x; k < DIN0; k += blockDim.x) {
        float v;
        if (k < 300) v = we[(size_t)w * 300 + k];
        else         v = pe[(size_t)p * 100 + (k - 300)];
        g_emb[(size_t)l * DIN0 + k] = v;
    }
}

// ---------------------------------------------------------------------------
// SGEMM: C = A @ W^T + bias.  A:[M,K], W:[N,K] row-major. K % 16 == 0,
// M % 128 == 0, N % 64 == 0. 128x64 tile, BK=16, 256 threads, 8x4 microtile.
// k-major smem (+4 pad) -> conflict-free; float4 global loads + float4 LDS.
// ---------------------------------------------------------------------------
#define BM 128
#define BN 64
#define BK 16
#define PADT 4
__global__ void __launch_bounds__(256)
sgemm_bias_kernel(const float* __restrict__ A, const float* __restrict__ W,
                  const float* __restrict__ bias, float* __restrict__ C,
                  int M, int N, int K,
                  long long sA, long long sW, long long sB, long long sC)
{
    int z = blockIdx.z;
    A    += (size_t)z * sA;
    W    += (size_t)z * sW;
    bias += (size_t)z * sB;
    C    += (size_t)z * sC;

    const int n0 = blockIdx.x * BN;
    const int m0 = blockIdx.y * BM;

    __shared__ float As[BK][BM + PADT];   // k-major
    __shared__ float Ws[BK][BN + PADT];

    const int tid = threadIdx.x;
    const int tx  = tid & 15;          // n group (4 cols)
    const int ty  = tid >> 4;          // m group (8 rows)

    float acc[8][4];
#pragma unroll
    for (int i = 0; i < 8; i++)
#pragma unroll
        for (int j = 0; j < 4; j++) acc[i][j] = 0.f;

    for (int k0 = 0; k0 < K; k0 += BK) {
        // A tile: 128 rows x 16 k = 512 float4, 2 per thread
#pragma unroll
        for (int s = 0; s < 2; s++) {
            int f4i = tid + s * 256;
            int m   = f4i >> 2;
            int kq  = (f4i & 3) << 2;
            float4 v = *(const float4*)&A[(size_t)(m0 + m) * K + k0 + kq];
            As[kq + 0][m] = v.x;
            As[kq + 1][m] = v.y;
            As[kq + 2][m] = v.z;
            As[kq + 3][m] = v.w;
        }
        // W tile: 64 rows x 16 k = 256 float4, 1 per thread
        {
            int n  = tid >> 2;
            int kq = (tid & 3) << 2;
            float4 v = *(const float4*)&W[(size_t)(n0 + n) * K + k0 + kq];
            Ws[kq + 0][n] = v.x;
            Ws[kq + 1][n] = v.y;
            Ws[kq + 2][n] = v.z;
            Ws[kq + 3][n] = v.w;
        }
        __syncthreads();
#pragma unroll
        for (int k = 0; k < BK; k++) {
            float4 a0 = *(const float4*)&As[k][ty * 8];
            float4 a1 = *(const float4*)&As[k][ty * 8 + 4];
            float4 b  = *(const float4*)&Ws[k][tx * 4];
            float a[8] = {a0.x, a0.y, a0.z, a0.w, a1.x, a1.y, a1.z, a1.w};
            float bb[4] = {b.x, b.y, b.z, b.w};
#pragma unroll
            for (int i = 0; i < 8; i++)
#pragma unroll
                for (int j = 0; j < 4; j++) acc[i][j] = fmaf(a[i], bb[j], acc[i][j]);
        }
        __syncthreads();
    }

#pragma unroll
    for (int i = 0; i < 8; i++) {
        int m = m0 + ty * 8 + i;
        int n = n0 + tx * 4;
        float4 o;
        o.x = acc[i][0] + bias[n + 0];
        o.y = acc[i][1] + bias[n + 1];
        o.z = acc[i][2] + bias[n + 2];
        o.w = acc[i][3] + bias[n + 3];
        *(float4*)&C[(size_t)m * N + n] = o;
    }
}

// ---------------------------------------------------------------------------
// Flag reset before each recurrence launch (graph-replay safe)
// ---------------------------------------------------------------------------
__global__ void reset_flags_kernel()
{
    if (threadIdx.x < 2 * NCTA_DIR) g_flags[threadIdx.x] = 0;
}

// ---------------------------------------------------------------------------
// Persistent bidirectional LSTM layer, register-resident Whh slice.
// Identical sync structure to the Round-3 kernel that PASSED, except the
// poll backoff only engages after 16 consecutive misses (R3 slept on the
// 2nd miss, which hit the coarse nanosleep quantum on every step).
// ---------------------------------------------------------------------------
__global__ void __launch_bounds__(256, 1)
lstm_layer_kernel(const float* __restrict__ Whh,   // [2][2048][512]
                  const float* __restrict__ xp,    // [2][L][2048] (bias folded in)
                  float* __restrict__ hcat)        // [L][1024]
{
    __shared__ float h_s[8][64];        // per-warp h chunk staging
    __shared__ float part[2][8][32];    // per-warp partial sums (parity)
    __shared__ float xp_s[2][32];       // xp for 32 rows (parity)

    const int tid  = threadIdx.x;
    const int wid  = tid >> 5;
    const int lane = tid & 31;
    const int b    = blockIdx.x;
    const int d    = b >> 6;
    const int cb   = b & 63;
    const int j0   = cb * JV;

    // --- stage this thread's 64 weights into registers ---
    float4 wr[16];
    {
        const int gate = lane >> 3, jl = lane & 7;
        const float4* src = (const float4*)(Whh +
            ((size_t)d * G4H + (size_t)gate * HDIRQ + j0 + jl) * HDIRQ + wid * 64);
#pragma unroll
        for (int i = 0; i < 16; i++) wr[i] = src[i];
    }

    float c_state = 0.f;                               // lanes 0..7 of warp 0
    int* const myflag = g_flags + d * NCTA_DIR + cb;
    const int* const pollp = g_flags + d * NCTA_DIR + (wid << 3) + (lane & 7);

    for (int step = 0; step < LQ; step++) {
        const int t = (d == 0) ? step : (LQ - 1 - step);
        const int p = step & 1;

        // prefetch xp (warp 1), issued before the poll so latency overlaps
        float xpv = 0.f;
        if (wid == 1) {
            const int gate = lane >> 3, jl = lane & 7;
            xpv = __ldg(xp + ((size_t)d * LQ + t) * G4H +
                        (size_t)gate * HDIRQ + j0 + jl);
        }

        float acc0 = 0.f, acc1 = 0.f, acc2 = 0.f, acc3 = 0.f;
        if (step > 0) {
            // wait for this warp's 8 chunk producers (acquire); free spin,
            // backoff only after 16 consecutive misses (never in steady state)
            int miss = 0;
            for (;;) {
                int v = step;
                if (lane < 8)
                    asm volatile("ld.acquire.gpu.global.s32 %0, [%1];"
                                 : "=r"(v) : "l"(pollp));
                if (__all_sync(0xffffffffu, v >= step)) break;
                if (++miss > 16) { __nanosleep(64); miss = 0; }
            }
            const int tp = (d == 0) ? (t - 1) : (t + 1);
            float2 hv = *(const float2*)(hcat + (size_t)tp * HIDQ + d * HDIRQ +
                                         (wid << 6) + lane * 2);
            ((float2*)h_s[wid])[lane] = hv;
            __syncwarp();
            const float4* hs4 = (const float4*)h_s[wid];
#pragma unroll
            for (int i = 0; i < 4; i++) {
                float4 h0 = hs4[4 * i + 0], h1 = hs4[4 * i + 1];
                float4 h2 = hs4[4 * i + 2], h3 = hs4[4 * i + 3];
                float4 w0 = wr[4 * i + 0], w1 = wr[4 * i + 1];
                float4 w2 = wr[4 * i + 2], w3 = wr[4 * i + 3];
                acc0 = fmaf(w0.x, h0.x, acc0); acc0 = fmaf(w0.y, h0.y, acc0);
                acc0 = fmaf(w0.z, h0.z, acc0); acc0 = fmaf(w0.w, h0.w, acc0);
                acc1 = fmaf(w1.x, h1.x, acc1); acc1 = fmaf(w1.y, h1.y, acc1);
                acc1 = fmaf(w1.z, h1.z, acc1); acc1 = fmaf(w1.w, h1.w, acc1);
                acc2 = fmaf(w2.x, h2.x, acc2); acc2 = fmaf(w2.y, h2.y, acc2);
                acc2 = fmaf(w2.z, h2.z, acc2); acc2 = fmaf(w2.w, h2.w, acc2);
                acc3 = fmaf(w3.x, h3.x, acc3); acc3 = fmaf(w3.y, h3.y, acc3);
                acc3 = fmaf(w3.z, h3.z, acc3); acc3 = fmaf(w3.w, h3.w, acc3);
            }
        }

        if (wid == 1) xp_s[p][lane] = xpv;
        part[p][wid][lane] = (acc0 + acc1) + (acc2 + acc3);
        __syncthreads();

        if (wid == 0) {
            float tot = 0.f;
#pragma unroll
            for (int w = 0; w < 8; w++) tot += part[p][w][lane];
            const int jj = lane & 7;
            float gi = __shfl_sync(0xffffffffu, tot, jj)      + xp_s[p][jj];
            float gf = __shfl_sync(0xffffffffu, tot, jj + 8)  + xp_s[p][8 + jj];
            float gg = __shfl_sync(0xffffffffu, tot, jj + 16) + xp_s[p][16 + jj];
            float go = __shfl_sync(0xffffffffu, tot, jj + 24) + xp_s[p][24 + jj];
            if (lane < 8) {
                float iv = fast_sigmoid(gi);
                float fv = fast_sigmoid(gf);
                float gv = fast_tanh(gg);
                float ov = fast_sigmoid(go);
                c_state = fv * c_state + iv * gv;
                float hv = ov * fast_tanh(c_state);
                hcat[(size_t)t * HIDQ + d * HDIRQ + j0 + lane] = hv;
            }
            __syncwarp();
            if (lane == 0) {
                int nv = step + 1;
                asm volatile("st.release.gpu.global.s32 [%0], %1;"
                             :: "l"(myflag), "r"(nv) : "memory");
            }
        }
    }
}

// ---------------------------------------------------------------------------
// s[l] = sum_n tanh(feat[l][n]) * wo[off + n]
// ---------------------------------------------------------------------------
__global__ void reduce_s_kernel(const float* __restrict__ feat, const float* __restrict__ wo,
                                int off, float* __restrict__ s)
{
    int l = blockIdx.x;
    int tid = threadIdx.x;
    float p = 0.f;
    for (int n = tid; n < MLPH; n += 256)
        p += tanhf(feat[(size_t)l * MLPH + n]) * wo[off + n];
    __shared__ float red[8];
#pragma unroll
    for (int o = 16; o > 0; o >>= 1) p += __shfl_xor_sync(0xffffffffu, p, o);
    if ((tid & 31) == 0) red[tid >> 5] = p;
    __syncthreads();
    if (tid < 8) {
        float v = red[tid];
#pragma unroll
        for (int o = 4; o > 0; o >>= 1) v += __shfl_xor_sync(0xffu, v, o);
        if (tid == 0) s[l] = v;
    }
}

// ---------------------------------------------------------------------------
// score[m][h] = s_modif[m] + s_head[h] + bo
// ---------------------------------------------------------------------------
__global__ void score_kernel(const float* __restrict__ sh, const float* __restrict__ sm,
                             const float* __restrict__ bo, float* __restrict__ out)
{
    int idx = blockIdx.x * 256 + threadIdx.x;
    int m = idx >> 10;
    int h = idx & 1023;
    out[idx] = sm[m] + sh[h] + bo[0];
}

// ---------------------------------------------------------------------------
// Launch sequence (graph-capturable)
// ---------------------------------------------------------------------------
extern "C" void kernel_launch(void* const* d_in, const int* in_sizes, int n_in,
                              void* d_out, int out_size)
{
    (void)in_sizes; (void)n_in; (void)out_size;

    const int*   wt   = (const int*)  d_in[0];
    const int*   pt   = (const int*)  d_in[1];
    const float* we   = (const float*)d_in[2];
    const float* pe   = (const float*)d_in[3];
    const float* Wih0 = (const float*)d_in[4];
    const float* Whh0 = (const float*)d_in[5];
    const float* b0   = (const float*)d_in[6];
    const float* Wih1 = (const float*)d_in[7];
    const float* Whh1 = (const float*)d_in[8];
    const float* b1   = (const float*)d_in[9];
    const float* Wh   = (const float*)d_in[10];
    const float* bh   = (const float*)d_in[11];
    const float* Wm   = (const float*)d_in[12];
    const float* bm   = (const float*)d_in[13];
    const float* wo   = (const float*)d_in[14];
    const float* bo   = (const float*)d_in[15];
    float*       out  = (float*)d_out;

    float *p_emb, *p_xp, *p_h0, *p_h1, *p_fH, *p_fM, *p_sh, *p_sm;
    cudaGetSymbolAddress((void**)&p_emb, g_emb);
    cudaGetSymbolAddress((void**)&p_xp,  g_xp);
    cudaGetSymbolAddress((void**)&p_h0,  g_hcat0);
    cudaGetSymbolAddress((void**)&p_h1,  g_hcat1);
    cudaGetSymbolAddress((void**)&p_fH,  g_featH);
    cudaGetSymbolAddress((void**)&p_fM,  g_featM);
    cudaGetSymbolAddress((void**)&p_sh,  g_shead);
    cudaGetSymbolAddress((void**)&p_sm,  g_smodif);

    // 1) embeddings
    embed_kernel<<<LQ, 128>>>(wt, pt, we, pe);

    // 2) layer-0 input projections
    {
        dim3 g(G4H / BN, LQ / BM, 2);
        sgemm_bias_kernel<<<g, 256>>>(p_emb, Wih0, b0, p_xp,
                                      LQ, G4H, DIN0,
                                      0LL, (long long)G4H * DIN0, (long long)G4H,
                                      (long long)LQ * G4H);
    }

    // 3) layer-0 recurrence
    reset_flags_kernel<<<1, 128>>>();
    lstm_layer_kernel<<<2 * NCTA_DIR, 256>>>(Whh0, p_xp, p_h0);

    // 4) layer-1 input projections
    {
        dim3 g(G4H / BN, LQ / BM, 2);
        sgemm_bias_kernel<<<g, 256>>>(p_h0, Wih1, b1, p_xp,
                                      LQ, G4H, HIDQ,
                                      0LL, (long long)G4H * HIDQ, (long long)G4H,
                                      (long long)LQ * G4H);
    }

    // 5) layer-1 recurrence
    reset_flags_kernel<<<1, 128>>>();
    lstm_layer_kernel<<<2 * NCTA_DIR, 256>>>(Whh1, p_xp, p_h1);

    // 6) MLP head features
    {
        dim3 g(MLPH / BN, LQ / BM, 1);
        sgemm_bias_kernel<<<g, 256>>>(p_h1, Wh, bh, p_fH, LQ, MLPH, HIDQ, 0LL, 0LL, 0LL, 0LL);
        sgemm_bias_kernel<<<g, 256>>>(p_h1, Wm, bm, p_fM, LQ, MLPH, HIDQ, 0LL, 0LL, 0LL, 0LL);
    }

    // 7) tanh-dot reductions
    reduce_s_kernel<<<LQ, 256>>>(p_fH, wo, 0,    p_sh);
    reduce_s_kernel<<<LQ, 256>>>(p_fM, wo, MLPH, p_sm);

    // 8) broadcast score matrix
    score_kernel<<<(LQ * LQ) / 256, 256>>>(p_sh, p_sm, bo, out);
}

// round 7
// speedup vs baseline: 3.4355x; 3.4355x over previous
#include <cuda_runtime.h>
#include <math.h>
#include <stdint.h>

// ---------------------------------------------------------------------------
// Shapes (fixed by the problem)
// ---------------------------------------------------------------------------
#define LQ    1024      // sentence length
#define HIDQ  1024      // bidirectional hidden
#define HDIRQ 512       // per-direction hidden
#define DIN0  400       // WDIM + PDIM
#define MLPH  512       // MLP/2
#define G4H   2048      // 4 * HDIR

// Recurrence geometry: 128 CTAs (64/dir), 256 thr. CTA owns 8 h-elems
// (32 gate rows). Warp w <-> h-chunk [w*64, w*64+64); lane <-> gate row.
#define NCTA_DIR 64
#define JV       8
#define FPAD     32     // ints per flag slot (128B line) -> no LTS hotspot

// ---------------------------------------------------------------------------
// Device scratch (no allocations allowed -> __device__ globals)
// ---------------------------------------------------------------------------
__device__ float g_emb[LQ * DIN0];
__device__ float g_xp[2 * LQ * G4H];
__device__ float g_hcat0[LQ * HIDQ];
__device__ float g_hcat1[LQ * HIDQ];
__device__ float g_featH[LQ * MLPH];
__device__ float g_featM[LQ * MLPH];
__device__ float g_shead[LQ];
__device__ float g_smodif[LQ];
__device__ __align__(128) int g_flags[2 * NCTA_DIR * FPAD];   // 16 KB, 1 flag / 128B line

__device__ __forceinline__ float fast_sigmoid(float x)
{
    return 1.f / (1.f + __expf(-x));
}
__device__ __forceinline__ float fast_tanh(float x)
{
    float e = __expf(-2.f * x);
    return (1.f - e) / (1.f + e);
}

// ---------------------------------------------------------------------------
// Embedding gather
// ---------------------------------------------------------------------------
__global__ void embed_kernel(const int* __restrict__ wt, const int* __restrict__ pt,
                             const float* __restrict__ we, const float* __restrict__ pe)
{
    int l = blockIdx.x;
    int w = wt[l];
    int p = pt[l];
    for (int k = threadIdx.x; k < DIN0; k += blockDim.x) {
        float v;
        if (k < 300) v = we[(size_t)w * 300 + k];
        else         v = pe[(size_t)p * 100 + (k - 300)];
        g_emb[(size_t)l * DIN0 + k] = v;
    }
}

// ---------------------------------------------------------------------------
// SGEMM: C = A @ W^T + bias.  A:[M,K], W:[N,K] row-major. K % 16 == 0,
// M % 128 == 0, N % 64 == 0. 128x64 tile, BK=16, 256 threads, 8x4 microtile.
// k-major smem (+4 pad) -> conflict-free; float4 global loads + float4 LDS.
// ---------------------------------------------------------------------------
#define BM 128
#define BN 64
#define BK 16
#define PADT 4
__global__ void __launch_bounds__(256)
sgemm_bias_kernel(const float* __restrict__ A, const float* __restrict__ W,
                  const float* __restrict__ bias, float* __restrict__ C,
                  int M, int N, int K,
                  long long sA, long long sW, long long sB, long long sC)
{
    int z = blockIdx.z;
    A    += (size_t)z * sA;
    W    += (size_t)z * sW;
    bias += (size_t)z * sB;
    C    += (size_t)z * sC;

    const int n0 = blockIdx.x * BN;
    const int m0 = blockIdx.y * BM;

    __shared__ float As[BK][BM + PADT];   // k-major
    __shared__ float Ws[BK][BN + PADT];

    const int tid = threadIdx.x;
    const int tx  = tid & 15;          // n group (4 cols)
    const int ty  = tid >> 4;          // m group (8 rows)

    float acc[8][4];
#pragma unroll
    for (int i = 0; i < 8; i++)
#pragma unroll
        for (int j = 0; j < 4; j++) acc[i][j] = 0.f;

    for (int k0 = 0; k0 < K; k0 += BK) {
        // A tile: 128 rows x 16 k = 512 float4, 2 per thread
#pragma unroll
        for (int s = 0; s < 2; s++) {
            int f4i = tid + s * 256;
            int m   = f4i >> 2;
            int kq  = (f4i & 3) << 2;
            float4 v = *(const float4*)&A[(size_t)(m0 + m) * K + k0 + kq];
            As[kq + 0][m] = v.x;
            As[kq + 1][m] = v.y;
            As[kq + 2][m] = v.z;
            As[kq + 3][m] = v.w;
        }
        // W tile: 64 rows x 16 k = 256 float4, 1 per thread
        {
            int n  = tid >> 2;
            int kq = (tid & 3) << 2;
            float4 v = *(const float4*)&W[(size_t)(n0 + n) * K + k0 + kq];
            Ws[kq + 0][n] = v.x;
            Ws[kq + 1][n] = v.y;
            Ws[kq + 2][n] = v.z;
            Ws[kq + 3][n] = v.w;
        }
        __syncthreads();
#pragma unroll
        for (int k = 0; k < BK; k++) {
            float4 a0 = *(const float4*)&As[k][ty * 8];
            float4 a1 = *(const float4*)&As[k][ty * 8 + 4];
            float4 b  = *(const float4*)&Ws[k][tx * 4];
            float a[8] = {a0.x, a0.y, a0.z, a0.w, a1.x, a1.y, a1.z, a1.w};
            float bb[4] = {b.x, b.y, b.z, b.w};
#pragma unroll
            for (int i = 0; i < 8; i++)
#pragma unroll
                for (int j = 0; j < 4; j++) acc[i][j] = fmaf(a[i], bb[j], acc[i][j]);
        }
        __syncthreads();
    }

#pragma unroll
    for (int i = 0; i < 8; i++) {
        int m = m0 + ty * 8 + i;
        int n = n0 + tx * 4;
        float4 o;
        o.x = acc[i][0] + bias[n + 0];
        o.y = acc[i][1] + bias[n + 1];
        o.z = acc[i][2] + bias[n + 2];
        o.w = acc[i][3] + bias[n + 3];
        *(float4*)&C[(size_t)m * N + n] = o;
    }
}

// ---------------------------------------------------------------------------
// Flag reset before each recurrence launch (graph-replay safe)
// ---------------------------------------------------------------------------
__global__ void reset_flags_kernel()
{
    int i = blockIdx.x * 256 + threadIdx.x;
    if (i < 2 * NCTA_DIR * FPAD) g_flags[i] = 0;
}

// ---------------------------------------------------------------------------
// Persistent bidirectional LSTM layer, register-resident Whh slice.
// Sync identical to passing R1/R3/R6 lineage, but each producer flag now
// owns a full 128B line so the poll traffic spreads over 128 L2 lines
// instead of hammering 2 (the R6 regression mechanism).
// ---------------------------------------------------------------------------
__global__ void __launch_bounds__(256, 1)
lstm_layer_kernel(const float* __restrict__ Whh,   // [2][2048][512]
                  const float* __restrict__ xp,    // [2][L][2048] (bias folded in)
                  float* __restrict__ hcat)        // [L][1024]
{
    __shared__ float h_s[8][64];        // per-warp h chunk staging
    __shared__ float part[2][8][32];    // per-warp partial sums (parity)
    __shared__ float xp_s[2][32];       // xp for 32 rows (parity)

    const int tid  = threadIdx.x;
    const int wid  = tid >> 5;
    const int lane = tid & 31;
    const int b    = blockIdx.x;
    const int d    = b >> 6;
    const int cb   = b & 63;
    const int j0   = cb * JV;

    // --- stage this thread's 64 weights into registers ---
    float4 wr[16];
    {
        const int gate = lane >> 3, jl = lane & 7;
        const float4* src = (const float4*)(Whh +
            ((size_t)d * G4H + (size_t)gate * HDIRQ + j0 + jl) * HDIRQ + wid * 64);
#pragma unroll
        for (int i = 0; i < 16; i++) wr[i] = src[i];
    }

    float c_state = 0.f;                               // lanes 0..7 of warp 0
    int* const myflag = g_flags + (d * NCTA_DIR + cb) * FPAD;
    const int* const pollp = g_flags +
        (d * NCTA_DIR + (wid << 3) + (lane & 7)) * FPAD;

    for (int step = 0; step < LQ; step++) {
        const int t = (d == 0) ? step : (LQ - 1 - step);
        const int p = step & 1;

        // prefetch xp (warp 1), issued before the poll so latency overlaps
        float xpv = 0.f;
        if (wid == 1) {
            const int gate = lane >> 3, jl = lane & 7;
            xpv = __ldg(xp + ((size_t)d * LQ + t) * G4H +
                        (size_t)gate * HDIRQ + j0 + jl);
        }

        float acc0 = 0.f, acc1 = 0.f, acc2 = 0.f, acc3 = 0.f;
        if (step > 0) {
            // wait for this warp's 8 chunk producers (acquire); free spin,
            // deep safety valve only (never fires in steady state)
            int miss = 0;
            for (;;) {
                int v = step;
                if (lane < 8)
                    asm volatile("ld.acquire.gpu.global.s32 %0, [%1];"
                                 : "=r"(v) : "l"(pollp));
                if (__all_sync(0xffffffffu, v >= step)) break;
                if (++miss > 256) { __nanosleep(128); miss = 0; }
            }
            const int tp = (d == 0) ? (t - 1) : (t + 1);
            float2 hv = *(const float2*)(hcat + (size_t)tp * HIDQ + d * HDIRQ +
                                         (wid << 6) + lane * 2);
            ((float2*)h_s[wid])[lane] = hv;
            __syncwarp();
            const float4* hs4 = (const float4*)h_s[wid];
#pragma unroll
            for (int i = 0; i < 4; i++) {
                float4 h0 = hs4[4 * i + 0], h1 = hs4[4 * i + 1];
                float4 h2 = hs4[4 * i + 2], h3 = hs4[4 * i + 3];
                float4 w0 = wr[4 * i + 0], w1 = wr[4 * i + 1];
                float4 w2 = wr[4 * i + 2], w3 = wr[4 * i + 3];
                acc0 = fmaf(w0.x, h0.x, acc0); acc0 = fmaf(w0.y, h0.y, acc0);
                acc0 = fmaf(w0.z, h0.z, acc0); acc0 = fmaf(w0.w, h0.w, acc0);
                acc1 = fmaf(w1.x, h1.x, acc1); acc1 = fmaf(w1.y, h1.y, acc1);
                acc1 = fmaf(w1.z, h1.z, acc1); acc1 = fmaf(w1.w, h1.w, acc1);
                acc2 = fmaf(w2.x, h2.x, acc2); acc2 = fmaf(w2.y, h2.y, acc2);
                acc2 = fmaf(w2.z, h2.z, acc2); acc2 = fmaf(w2.w, h2.w, acc2);
                acc3 = fmaf(w3.x, h3.x, acc3); acc3 = fmaf(w3.y, h3.y, acc3);
                acc3 = fmaf(w3.z, h3.z, acc3); acc3 = fmaf(w3.w, h3.w, acc3);
            }
        }

        if (wid == 1) xp_s[p][lane] = xpv;
        part[p][wid][lane] = (acc0 + acc1) + (acc2 + acc3);
        __syncthreads();

        if (wid == 0) {
            float tot = 0.f;
#pragma unroll
            for (int w = 0; w < 8; w++) tot += part[p][w][lane];
            const int jj = lane & 7;
            float gi = __shfl_sync(0xffffffffu, tot, jj)      + xp_s[p][jj];
            float gf = __shfl_sync(0xffffffffu, tot, jj + 8)  + xp_s[p][8 + jj];
            float gg = __shfl_sync(0xffffffffu, tot, jj + 16) + xp_s[p][16 + jj];
            float go = __shfl_sync(0xffffffffu, tot, jj + 24) + xp_s[p][24 + jj];
            if (lane < 8) {
                float iv = fast_sigmoid(gi);
                float fv = fast_sigmoid(gf);
                float gv = fast_tanh(gg);
                float ov = fast_sigmoid(go);
                c_state = fv * c_state + iv * gv;
                float hv = ov * fast_tanh(c_state);
                hcat[(size_t)t * HIDQ + d * HDIRQ + j0 + lane] = hv;
            }
            __syncwarp();
            if (lane == 0) {
                int nv = step + 1;
                asm volatile("st.release.gpu.global.s32 [%0], %1;"
                             :: "l"(myflag), "r"(nv) : "memory");
            }
        }
    }
}

// ---------------------------------------------------------------------------
// s[l] = sum_n tanh(feat[l][n]) * wo[off + n]
// ---------------------------------------------------------------------------
__global__ void reduce_s_kernel(const float* __restrict__ feat, const float* __restrict__ wo,
                                int off, float* __restrict__ s)
{
    int l = blockIdx.x;
    int tid = threadIdx.x;
    float p = 0.f;
    for (int n = tid; n < MLPH; n += 256)
        p += tanhf(feat[(size_t)l * MLPH + n]) * wo[off + n];
    __shared__ float red[8];
#pragma unroll
    for (int o = 16; o > 0; o >>= 1) p += __shfl_xor_sync(0xffffffffu, p, o);
    if ((tid & 31) == 0) red[tid >> 5] = p;
    __syncthreads();
    if (tid < 8) {
        float v = red[tid];
#pragma unroll
        for (int o = 4; o > 0; o >>= 1) v += __shfl_xor_sync(0xffu, v, o);
        if (tid == 0) s[l] = v;
    }
}

// ---------------------------------------------------------------------------
// score[m][h] = s_modif[m] + s_head[h] + bo
// ---------------------------------------------------------------------------
__global__ void score_kernel(const float* __restrict__ sh, const float* __restrict__ sm,
                             const float* __restrict__ bo, float* __restrict__ out)
{
    int idx = blockIdx.x * 256 + threadIdx.x;
    int m = idx >> 10;
    int h = idx & 1023;
    out[idx] = sm[m] + sh[h] + bo[0];
}

// ---------------------------------------------------------------------------
// Launch sequence (graph-capturable)
// ---------------------------------------------------------------------------
extern "C" void kernel_launch(void* const* d_in, const int* in_sizes, int n_in,
                              void* d_out, int out_size)
{
    (void)in_sizes; (void)n_in; (void)out_size;

    const int*   wt   = (const int*)  d_in[0];
    const int*   pt   = (const int*)  d_in[1];
    const float* we   = (const float*)d_in[2];
    const float* pe   = (const float*)d_in[3];
    const float* Wih0 = (const float*)d_in[4];
    const float* Whh0 = (const float*)d_in[5];
    const float* b0   = (const float*)d_in[6];
    const float* Wih1 = (const float*)d_in[7];
    const float* Whh1 = (const float*)d_in[8];
    const float* b1   = (const float*)d_in[9];
    const float* Wh   = (const float*)d_in[10];
    const float* bh   = (const float*)d_in[11];
    const float* Wm   = (const float*)d_in[12];
    const float* bm   = (const float*)d_in[13];
    const float* wo   = (const float*)d_in[14];
    const float* bo   = (const float*)d_in[15];
    float*       out  = (float*)d_out;

    float *p_emb, *p_xp, *p_h0, *p_h1, *p_fH, *p_fM, *p_sh, *p_sm;
    cudaGetSymbolAddress((void**)&p_emb, g_emb);
    cudaGetSymbolAddress((void**)&p_xp,  g_xp);
    cudaGetSymbolAddress((void**)&p_h0,  g_hcat0);
    cudaGetSymbolAddress((void**)&p_h1,  g_hcat1);
    cudaGetSymbolAddress((void**)&p_fH,  g_featH);
    cudaGetSymbolAddress((void**)&p_fM,  g_featM);
    cudaGetSymbolAddress((void**)&p_sh,  g_shead);
    cudaGetSymbolAddress((void**)&p_sm,  g_smodif);

    // 1) embeddings
    embed_kernel<<<LQ, 128>>>(wt, pt, we, pe);

    // 2) layer-0 input projections
    {
        dim3 g(G4H / BN, LQ / BM, 2);
        sgemm_bias_kernel<<<g, 256>>>(p_emb, Wih0, b0, p_xp,
                                      LQ, G4H, DIN0,
                                      0LL, (long long)G4H * DIN0, (long long)G4H,
                                      (long long)LQ * G4H);
    }

    // 3) layer-0 recurrence
    reset_flags_kernel<<<(2 * NCTA_DIR * FPAD + 255) / 256, 256>>>();
    lstm_layer_kernel<<<2 * NCTA_DIR, 256>>>(Whh0, p_xp, p_h0);

    // 4) layer-1 input projections
    {
        dim3 g(G4H / BN, LQ / BM, 2);
        sgemm_bias_kernel<<<g, 256>>>(p_h0, Wih1, b1, p_xp,
                                      LQ, G4H, HIDQ,
                                      0LL, (long long)G4H * HIDQ, (long long)G4H,
                                      (long long)LQ * G4H);
    }

    // 5) layer-1 recurrence
    reset_flags_kernel<<<(2 * NCTA_DIR * FPAD + 255) / 256, 256>>>();
    lstm_layer_kernel<<<2 * NCTA_DIR, 256>>>(Whh1, p_xp, p_h1);

    // 6) MLP head features
    {
        dim3 g(MLPH / BN, LQ / BM, 1);
        sgemm_bias_kernel<<<g, 256>>>(p_h1, Wh, bh, p_fH, LQ, MLPH, HIDQ, 0LL, 0LL, 0LL, 0LL);
        sgemm_bias_kernel<<<g, 256>>>(p_h1, Wm, bm, p_fM, LQ, MLPH, HIDQ, 0LL, 0LL, 0LL, 0LL);
    }

    // 7) tanh-dot reductions
    reduce_s_kernel<<<LQ, 256>>>(p_fH, wo, 0,    p_sh);
    reduce_s_kernel<<<LQ, 256>>>(p_fM, wo, MLPH, p_sm);

    // 8) broadcast score matrix
    score_kernel<<<(LQ * LQ) / 256, 256>>>(p_sh, p_sm, bo, out);
}

// round 9
// speedup vs baseline: 3.4749x; 1.0115x over previous
#include <cuda_runtime.h>
#include <math.h>
#include <stdint.h>

// ---------------------------------------------------------------------------
// Shapes (fixed by the problem)
// ---------------------------------------------------------------------------
#define LQ    1024      // sentence length
#define HIDQ  1024      // bidirectional hidden
#define HDIRQ 512       // per-direction hidden
#define DIN0  400       // WDIM + PDIM
#define MLPH  512       // MLP/2
#define G4H   2048      // 4 * HDIR

// Recurrence geometry: 128 CTAs (64/dir), 256 thr. CTA owns 8 h-elems
// (32 gate rows). Warp w <-> h-chunk [w*64, w*64+64); lane <-> gate row.
#define NCTA_DIR 64
#define JV       8
#define FPAD     32     // ints per flag slot (128B line) -> no LTS hotspot

// ---------------------------------------------------------------------------
// Device scratch (no allocations allowed -> __device__ globals)
// ---------------------------------------------------------------------------
__device__ float g_emb[LQ * DIN0];
__device__ float g_xp[2 * LQ * G4H];
__device__ float g_hcat0[LQ * HIDQ];
__device__ float g_hcat1[LQ * HIDQ];
__device__ float g_featH[LQ * MLPH];
__device__ float g_featM[LQ * MLPH];
__device__ float g_shead[LQ];
__device__ float g_smodif[LQ];
__device__ __align__(128) int g_flags[2 * NCTA_DIR * FPAD];   // 16 KB, 1 flag / 128B line

__device__ __forceinline__ float fast_sigmoid(float x)
{
    return 1.f / (1.f + __expf(-x));
}
__device__ __forceinline__ float fast_tanh(float x)
{
    float e = __expf(-2.f * x);
    return (1.f - e) / (1.f + e);
}

// ---------------------------------------------------------------------------
// Embedding gather
// ---------------------------------------------------------------------------
__global__ void embed_kernel(const int* __restrict__ wt, const int* __restrict__ pt,
                             const float* __restrict__ we, const float* __restrict__ pe)
{
    int l = blockIdx.x;
    int w = wt[l];
    int p = pt[l];
    for (int k = threadIdx.x; k < DIN0; k += blockDim.x) {
        float v;
        if (k < 300) v = we[(size_t)w * 300 + k];
        else         v = pe[(size_t)p * 100 + (k - 300)];
        g_emb[(size_t)l * DIN0 + k] = v;
    }
}

// ---------------------------------------------------------------------------
// SGEMM: C = A @ W^T + bias.  A:[M,K], W:[N,K] row-major. K % 16 == 0,
// M % 128 == 0, N % 64 == 0. 128x64 tile, BK=16, 256 threads, 8x4 microtile.
// Double-buffered smem stages + register prefetch: one __syncthreads per
// K-tile, next-tile LDG overlaps current-tile FMA.
// ---------------------------------------------------------------------------
#define BM 128
#define BN 64
#define BK 16
#define PADT 4
__global__ void __launch_bounds__(256)
sgemm_bias_kernel(const float* __restrict__ A, const float* __restrict__ W,
                  const float* __restrict__ bias, float* __restrict__ C,
                  int M, int N, int K,
                  long long sA, long long sW, long long sB, long long sC)
{
    int z = blockIdx.z;
    A    += (size_t)z * sA;
    W    += (size_t)z * sW;
    bias += (size_t)z * sB;
    C    += (size_t)z * sC;

    const int n0 = blockIdx.x * BN;
    const int m0 = blockIdx.y * BM;

    __shared__ float As[2][BK][BM + PADT];   // k-major, 2 stages
    __shared__ float Ws[2][BK][BN + PADT];

    const int tid = threadIdx.x;
    const int tx  = tid & 15;          // n group (4 cols)
    const int ty  = tid >> 4;          // m group (8 rows)

    const int am0 = tid >> 2;                 // A f4 row (first half)
    const int akq = (tid & 3) << 2;           // A k quad
    const int wn  = tid >> 2;                 // W row
    const int wkq = (tid & 3) << 2;           // W k quad

    float acc[8][4];
#pragma unroll
    for (int i = 0; i < 8; i++)
#pragma unroll
        for (int j = 0; j < 4; j++) acc[i][j] = 0.f;

    const int ntiles = K / BK;

    // prologue: tile 0 -> regs -> stage 0
    float4 a_r0 = *(const float4*)&A[(size_t)(m0 + am0) * K + akq];
    float4 a_r1 = *(const float4*)&A[(size_t)(m0 + am0 + 64) * K + akq];
    float4 w_r  = *(const float4*)&W[(size_t)(n0 + wn) * K + wkq];
    {
        As[0][akq + 0][am0] = a_r0.x; As[0][akq + 1][am0] = a_r0.y;
        As[0][akq + 2][am0] = a_r0.z; As[0][akq + 3][am0] = a_r0.w;
        As[0][akq + 0][am0 + 64] = a_r1.x; As[0][akq + 1][am0 + 64] = a_r1.y;
        As[0][akq + 2][am0 + 64] = a_r1.z; As[0][akq + 3][am0 + 64] = a_r1.w;
        Ws[0][wkq + 0][wn] = w_r.x; Ws[0][wkq + 1][wn] = w_r.y;
        Ws[0][wkq + 2][wn] = w_r.z; Ws[0][wkq + 3][wn] = w_r.w;
    }
    __syncthreads();

    int cur = 0;
    for (int tI = 0; tI < ntiles; tI++) {
        const bool has_next = (tI + 1) < ntiles;
        if (has_next) {
            int k0n = (tI + 1) * BK;
            a_r0 = *(const float4*)&A[(size_t)(m0 + am0) * K + k0n + akq];
            a_r1 = *(const float4*)&A[(size_t)(m0 + am0 + 64) * K + k0n + akq];
            w_r  = *(const float4*)&W[(size_t)(n0 + wn) * K + k0n + wkq];
        }
#pragma unroll
        for (int k = 0; k < BK; k++) {
            float4 a0 = *(const float4*)&As[cur][k][ty * 8];
            float4 a1 = *(const float4*)&As[cur][k][ty * 8 + 4];
            float4 b  = *(const float4*)&Ws[cur][k][tx * 4];
            float a[8] = {a0.x, a0.y, a0.z, a0.w, a1.x, a1.y, a1.z, a1.w};
            float bb[4] = {b.x, b.y, b.z, b.w};
#pragma unroll
            for (int i = 0; i < 8; i++)
#pragma unroll
                for (int j = 0; j < 4; j++) acc[i][j] = fmaf(a[i], bb[j], acc[i][j]);
        }
        if (has_next) {
            int nxt = cur ^ 1;
            As[nxt][akq + 0][am0] = a_r0.x; As[nxt][akq + 1][am0] = a_r0.y;
            As[nxt][akq + 2][am0] = a_r0.z; As[nxt][akq + 3][am0] = a_r0.w;
            As[nxt][akq + 0][am0 + 64] = a_r1.x; As[nxt][akq + 1][am0 + 64] = a_r1.y;
            As[nxt][akq + 2][am0 + 64] = a_r1.z; As[nxt][akq + 3][am0 + 64] = a_r1.w;
            Ws[nxt][wkq + 0][wn] = w_r.x; Ws[nxt][wkq + 1][wn] = w_r.y;
            Ws[nxt][wkq + 2][wn] = w_r.z; Ws[nxt][wkq + 3][wn] = w_r.w;
            __syncthreads();
            cur = nxt;
        }
    }

#pragma unroll
    for (int i = 0; i < 8; i++) {
        int m = m0 + ty * 8 + i;
        int n = n0 + tx * 4;
        float4 o;
        o.x = acc[i][0] + bias[n + 0];
        o.y = acc[i][1] + bias[n + 1];
        o.z = acc[i][2] + bias[n + 2];
        o.w = acc[i][3] + bias[n + 3];
        *(float4*)&C[(size_t)m * N + n] = o;
    }
}

// ---------------------------------------------------------------------------
// Flag reset before each recurrence launch (graph-replay safe)
// ---------------------------------------------------------------------------
__global__ void reset_flags_kernel()
{
    int i = blockIdx.x * 256 + threadIdx.x;
    if (i < 2 * NCTA_DIR * FPAD) g_flags[i] = 0;
}

// ---------------------------------------------------------------------------
// Persistent bidirectional LSTM layer — EXACTLY the Round-7 kernel that
// passed at 4937us. Padded per-producer flags (1 per 128B line), acquire
// polling, release publish. Do not touch without a new theory.
// ---------------------------------------------------------------------------
__global__ void __launch_bounds__(256, 1)
lstm_layer_kernel(const float* __restrict__ Whh,   // [2][2048][512]
                  const float* __restrict__ xp,    // [2][L][2048] (bias folded in)
                  float* __restrict__ hcat)        // [L][1024]
{
    __shared__ float h_s[8][64];        // per-warp h chunk staging
    __shared__ float part[2][8][32];    // per-warp partial sums (parity)
    __shared__ float xp_s[2][32];       // xp for 32 rows (parity)

    const int tid  = threadIdx.x;
    const int wid  = tid >> 5;
    const int lane = tid & 31;
    const int b    = blockIdx.x;
    const int d    = b >> 6;
    const int cb   = b & 63;
    const int j0   = cb * JV;

    // --- stage this thread's 64 weights into registers ---
    float4 wr[16];
    {
        const int gate = lane >> 3, jl = lane & 7;
        const float4* src = (const float4*)(Whh +
            ((size_t)d * G4H + (size_t)gate * HDIRQ + j0 + jl) * HDIRQ + wid * 64);
#pragma unroll
        for (int i = 0; i < 16; i++) wr[i] = src[i];
    }

    float c_state = 0.f;                               // lanes 0..7 of warp 0
    int* const myflag = g_flags + (d * NCTA_DIR + cb) * FPAD;
    const int* const pollp = g_flags +
        (d * NCTA_DIR + (wid << 3) + (lane & 7)) * FPAD;

    for (int step = 0; step < LQ; step++) {
        const int t = (d == 0) ? step : (LQ - 1 - step);
        const int p = step & 1;

        // prefetch xp (warp 1), issued before the poll so latency overlaps
        float xpv = 0.f;
        if (wid == 1) {
            const int gate = lane >> 3, jl = lane & 7;
            xpv = __ldg(xp + ((size_t)d * LQ + t) * G4H +
                        (size_t)gate * HDIRQ + j0 + jl);
        }

        float acc0 = 0.f, acc1 = 0.f, acc2 = 0.f, acc3 = 0.f;
        if (step > 0) {
            // wait for this warp's 8 chunk producers (acquire); free spin,
            // deep safety valve only (never fires in steady state)
            int miss = 0;
            for (;;) {
                int v = step;
                if (lane < 8)
                    asm volatile("ld.acquire.gpu.global.s32 %0, [%1];"
                                 : "=r"(v) : "l"(pollp));
                if (__all_sync(0xffffffffu, v >= step)) break;
                if (++miss > 256) { __nanosleep(128); miss = 0; }
            }
            const int tp = (d == 0) ? (t - 1) : (t + 1);
            float2 hv = *(const float2*)(hcat + (size_t)tp * HIDQ + d * HDIRQ +
                                         (wid << 6) + lane * 2);
            ((float2*)h_s[wid])[lane] = hv;
            __syncwarp();
            const float4* hs4 = (const float4*)h_s[wid];
#pragma unroll
            for (int i = 0; i < 4; i++) {
                float4 h0 = hs4[4 * i + 0], h1 = hs4[4 * i + 1];
                float4 h2 = hs4[4 * i + 2], h3 = hs4[4 * i + 3];
                float4 w0 = wr[4 * i + 0], w1 = wr[4 * i + 1];
                float4 w2 = wr[4 * i + 2], w3 = wr[4 * i + 3];
                acc0 = fmaf(w0.x, h0.x, acc0); acc0 = fmaf(w0.y, h0.y, acc0);
                acc0 = fmaf(w0.z, h0.z, acc0); acc0 = fmaf(w0.w, h0.w, acc0);
                acc1 = fmaf(w1.x, h1.x, acc1); acc1 = fmaf(w1.y, h1.y, acc1);
                acc1 = fmaf(w1.z, h1.z, acc1); acc1 = fmaf(w1.w, h1.w, acc1);
                acc2 = fmaf(w2.x, h2.x, acc2); acc2 = fmaf(w2.y, h2.y, acc2);
                acc2 = fmaf(w2.z, h2.z, acc2); acc2 = fmaf(w2.w, h2.w, acc2);
                acc3 = fmaf(w3.x, h3.x, acc3); acc3 = fmaf(w3.y, h3.y, acc3);
                acc3 = fmaf(w3.z, h3.z, acc3); acc3 = fmaf(w3.w, h3.w, acc3);
            }
        }

        if (wid == 1) xp_s[p][lane] = xpv;
        part[p][wid][lane] = (acc0 + acc1) + (acc2 + acc3);
        __syncthreads();

        if (wid == 0) {
            float tot = 0.f;
#pragma unroll
            for (int w = 0; w < 8; w++) tot += part[p][w][lane];
            const int jj = lane & 7;
            float gi = __shfl_sync(0xffffffffu, tot, jj)      + xp_s[p][jj];
            float gf = __shfl_sync(0xffffffffu, tot, jj + 8)  + xp_s[p][8 + jj];
            float gg = __shfl_sync(0xffffffffu, tot, jj + 16) + xp_s[p][16 + jj];
            float go = __shfl_sync(0xffffffffu, tot, jj + 24) + xp_s[p][24 + jj];
            if (lane < 8) {
                float iv = fast_sigmoid(gi);
                float fv = fast_sigmoid(gf);
                float gv = fast_tanh(gg);
                float ov = fast_sigmoid(go);
                c_state = fv * c_state + iv * gv;
                float hv = ov * fast_tanh(c_state);
                hcat[(size_t)t * HIDQ + d * HDIRQ + j0 + lane] = hv;
            }
            __syncwarp();
            if (lane == 0) {
                int nv = step + 1;
                asm volatile("st.release.gpu.global.s32 [%0], %1;"
                             :: "l"(myflag), "r"(nv) : "memory");
            }
        }
    }
}

// ---------------------------------------------------------------------------
// s[l] = sum_n tanh(feat[l][n]) * wo[off + n]
// ---------------------------------------------------------------------------
__global__ void reduce_s_kernel(const float* __restrict__ feat, const float* __restrict__ wo,
                                int off, float* __restrict__ s)
{
    int l = blockIdx.x;
    int tid = threadIdx.x;
    float p = 0.f;
    for (int n = tid; n < MLPH; n += 256)
        p += tanhf(feat[(size_t)l * MLPH + n]) * wo[off + n];
    __shared__ float red[8];
#pragma unroll
    for (int o = 16; o > 0; o >>= 1) p += __shfl_xor_sync(0xffffffffu, p, o);
    if ((tid & 31) == 0) red[tid >> 5] = p;
    __syncthreads();
    if (tid < 8) {
        float v = red[tid];
#pragma unroll
        for (int o = 4; o > 0; o >>= 1) v += __shfl_xor_sync(0xffu, v, o);
        if (tid == 0) s[l] = v;
    }
}

// ---------------------------------------------------------------------------
// score[m][h] = s_modif[m] + s_head[h] + bo
// ---------------------------------------------------------------------------
__global__ void score_kernel(const float* __restrict__ sh, const float* __restrict__ sm,
                             const float* __restrict__ bo, float* __restrict__ out)
{
    int idx = blockIdx.x * 256 + threadIdx.x;
    int m = idx >> 10;
    int h = idx & 1023;
    out[idx] = sm[m] + sh[h] + bo[0];
}

// ---------------------------------------------------------------------------
// Launch sequence (graph-capturable)
// ---------------------------------------------------------------------------
extern "C" void kernel_launch(void* const* d_in, const int* in_sizes, int n_in,
                              void* d_out, int out_size)
{
    (void)in_sizes; (void)n_in; (void)out_size;

    const int*   wt   = (const int*)  d_in[0];
    const int*   pt   = (const int*)  d_in[1];
    const float* we   = (const float*)d_in[2];
    const float* pe   = (const float*)d_in[3];
    const float* Wih0 = (const float*)d_in[4];
    const float* Whh0 = (const float*)d_in[5];
    const float* b0   = (const float*)d_in[6];
    const float* Wih1 = (const float*)d_in[7];
    const float* Whh1 = (const float*)d_in[8];
    const float* b1   = (const float*)d_in[9];
    const float* Wh   = (const float*)d_in[10];
    const float* bh   = (const float*)d_in[11];
    const float* Wm   = (const float*)d_in[12];
    const float* bm   = (const float*)d_in[13];
    const float* wo   = (const float*)d_in[14];
    const float* bo   = (const float*)d_in[15];
    float*       out  = (float*)d_out;

    float *p_emb, *p_xp, *p_h0, *p_h1, *p_fH, *p_fM, *p_sh, *p_sm;
    cudaGetSymbolAddress((void**)&p_emb, g_emb);
    cudaGetSymbolAddress((void**)&p_xp,  g_xp);
    cudaGetSymbolAddress((void**)&p_h0,  g_hcat0);
    cudaGetSymbolAddress((void**)&p_h1,  g_hcat1);
    cudaGetSymbolAddress((void**)&p_fH,  g_featH);
    cudaGetSymbolAddress((void**)&p_fM,  g_featM);
    cudaGetSymbolAddress((void**)&p_sh,  g_shead);
    cudaGetSymbolAddress((void**)&p_sm,  g_smodif);

    // 1) embeddings
    embed_kernel<<<LQ, 128>>>(wt, pt, we, pe);

    // 2) layer-0 input projections
    {
        dim3 g(G4H / BN, LQ / BM, 2);
        sgemm_bias_kernel<<<g, 256>>>(p_emb, Wih0, b0, p_xp,
                                      LQ, G4H, DIN0,
                                      0LL, (long long)G4H * DIN0, (long long)G4H,
                                      (long long)LQ * G4H);
    }

    // 3) layer-0 recurrence
    reset_flags_kernel<<<(2 * NCTA_DIR * FPAD + 255) / 256, 256>>>();
    lstm_layer_kernel<<<2 * NCTA_DIR, 256>>>(Whh0, p_xp, p_h0);

    // 4) layer-1 input projections
    {
        dim3 g(G4H / BN, LQ / BM, 2);
        sgemm_bias_kernel<<<g, 256>>>(p_h0, Wih1, b1, p_xp,
                                      LQ, G4H, HIDQ,
                                      0LL, (long long)G4H * HIDQ, (long long)G4H,
                                      (long long)LQ * G4H);
    }

    // 5) layer-1 recurrence
    reset_flags_kernel<<<(2 * NCTA_DIR * FPAD + 255) / 256, 256>>>();
    lstm_layer_kernel<<<2 * NCTA_DIR, 256>>>(Whh1, p_xp, p_h1);

    // 6) MLP head features
    {
        dim3 g(MLPH / BN, LQ / BM, 1);
        sgemm_bias_kernel<<<g, 256>>>(p_h1, Wh, bh, p_fH, LQ, MLPH, HIDQ, 0LL, 0LL, 0LL, 0LL);
        sgemm_bias_kernel<<<g, 256>>>(p_h1, Wm, bm, p_fM, LQ, MLPH, HIDQ, 0LL, 0LL, 0LL, 0LL);
    }

    // 7) tanh-dot reductions
    reduce_s_kernel<<<LQ, 256>>>(p_fH, wo, 0,    p_sh);
    reduce_s_kernel<<<LQ, 256>>>(p_fM, wo, MLPH, p_sm);

    // 8) broadcast score matrix
    score_kernel<<<(LQ * LQ) / 256, 256>>>(p_sh, p_sm, bo, out);
}

// round 10
// speedup vs baseline: 6.4949x; 1.8691x over previous
#include <cuda_runtime.h>
#include <math.h>
#include <stdint.h>

// ---------------------------------------------------------------------------
// Shapes (fixed by the problem)
// ---------------------------------------------------------------------------
#define LQ    1024      // sentence length
#define HIDQ  1024      // bidirectional hidden
#define HDIRQ 512       // per-direction hidden
#define DIN0  400       // WDIM + PDIM
#define MLPH  512       // MLP/2
#define G4H   2048      // 4 * HDIR

// Recurrence geometry: 128 CTAs (64/dir), 256 thr. CTA owns 8 h-elems
// (32 gate rows). Warp w <-> h-chunk [w*64, w*64+64); lane <-> gate row.
#define NCTA_DIR 64
#define JV       8
#define NANP     0x7FC00000u    // poison NaN: "value not yet written"

// ---------------------------------------------------------------------------
// Device scratch (no allocations allowed -> __device__ globals)
// ---------------------------------------------------------------------------
__device__ float g_emb[LQ * DIN0];
__device__ float g_xp[2 * LQ * G4H];
// layer outputs, hcat layout [t][d*512+j]; doubles as the sync medium:
// cleared to NANP before each recurrence, each word written exactly once.
__device__ __align__(128) float g_h0[LQ * HIDQ];
__device__ __align__(128) float g_h1[LQ * HIDQ];
__device__ float g_featH[LQ * MLPH];
__device__ float g_featM[LQ * MLPH];
__device__ float g_shead[LQ];
__device__ float g_smodif[LQ];

__device__ __forceinline__ float fast_sigmoid(float x)
{
    return __fdividef(1.f, 1.f + __expf(-x));
}
__device__ __forceinline__ float fast_tanh(float x)
{
    float e = __expf(-2.f * x);
    return __fdividef(1.f - e, 1.f + e);
}

// ---------------------------------------------------------------------------
// Embedding gather
// ---------------------------------------------------------------------------
__global__ void embed_kernel(const int* __restrict__ wt, const int* __restrict__ pt,
                             const float* __restrict__ we, const float* __restrict__ pe)
{
    int l = blockIdx.x;
    int w = wt[l];
    int p = pt[l];
    for (int k = threadIdx.x; k < DIN0; k += blockDim.x) {
        float v;
        if (k < 300) v = we[(size_t)w * 300 + k];
        else         v = pe[(size_t)p * 100 + (k - 300)];
        g_emb[(size_t)l * DIN0 + k] = v;
    }
}

// ---------------------------------------------------------------------------
// SGEMM: C = A @ W^T + bias.  A:[M,K], W:[N,K] row-major. K % 16 == 0,
// M % 128 == 0, N % 64 == 0. 128x64 tile, BK=16, 256 threads, 8x4 microtile.
// Double-buffered smem stages + register prefetch (unchanged from R9).
// ---------------------------------------------------------------------------
#define BM 128
#define BN 64
#define BK 16
#define PADT 4
__global__ void __launch_bounds__(256)
sgemm_bias_kernel(const float* __restrict__ A, const float* __restrict__ W,
                  const float* __restrict__ bias, float* __restrict__ C,
                  int M, int N, int K,
                  long long sA, long long sW, long long sB, long long sC)
{
    int z = blockIdx.z;
    A    += (size_t)z * sA;
    W    += (size_t)z * sW;
    bias += (size_t)z * sB;
    C    += (size_t)z * sC;

    const int n0 = blockIdx.x * BN;
    const int m0 = blockIdx.y * BM;

    __shared__ float As[2][BK][BM + PADT];   // k-major, 2 stages
    __shared__ float Ws[2][BK][BN + PADT];

    const int tid = threadIdx.x;
    const int tx  = tid & 15;          // n group (4 cols)
    const int ty  = tid >> 4;          // m group (8 rows)

    const int am0 = tid >> 2;                 // A f4 row (first half)
    const int akq = (tid & 3) << 2;           // A k quad
    const int wn  = tid >> 2;                 // W row
    const int wkq = (tid & 3) << 2;           // W k quad

    float acc[8][4];
#pragma unroll
    for (int i = 0; i < 8; i++)
#pragma unroll
        for (int j = 0; j < 4; j++) acc[i][j] = 0.f;

    const int ntiles = K / BK;

    float4 a_r0 = *(const float4*)&A[(size_t)(m0 + am0) * K + akq];
    float4 a_r1 = *(const float4*)&A[(size_t)(m0 + am0 + 64) * K + akq];
    float4 w_r  = *(const float4*)&W[(size_t)(n0 + wn) * K + wkq];
    {
        As[0][akq + 0][am0] = a_r0.x; As[0][akq + 1][am0] = a_r0.y;
        As[0][akq + 2][am0] = a_r0.z; As[0][akq + 3][am0] = a_r0.w;
        As[0][akq + 0][am0 + 64] = a_r1.x; As[0][akq + 1][am0 + 64] = a_r1.y;
        As[0][akq + 2][am0 + 64] = a_r1.z; As[0][akq + 3][am0 + 64] = a_r1.w;
        Ws[0][wkq + 0][wn] = w_r.x; Ws[0][wkq + 1][wn] = w_r.y;
        Ws[0][wkq + 2][wn] = w_r.z; Ws[0][wkq + 3][wn] = w_r.w;
    }
    __syncthreads();

    int cur = 0;
    for (int tI = 0; tI < ntiles; tI++) {
        const bool has_next = (tI + 1) < ntiles;
        if (has_next) {
            int k0n = (tI + 1) * BK;
            a_r0 = *(const float4*)&A[(size_t)(m0 + am0) * K + k0n + akq];
            a_r1 = *(const float4*)&A[(size_t)(m0 + am0 + 64) * K + k0n + akq];
            w_r  = *(const float4*)&W[(size_t)(n0 + wn) * K + k0n + wkq];
        }
#pragma unroll
        for (int k = 0; k < BK; k++) {
            float4 a0 = *(const float4*)&As[cur][k][ty * 8];
            float4 a1 = *(const float4*)&As[cur][k][ty * 8 + 4];
            float4 b  = *(const float4*)&Ws[cur][k][tx * 4];
            float a[8] = {a0.x, a0.y, a0.z, a0.w, a1.x, a1.y, a1.z, a1.w};
            float bb[4] = {b.x, b.y, b.z, b.w};
#pragma unroll
            for (int i = 0; i < 8; i++)
#pragma unroll
                for (int j = 0; j < 4; j++) acc[i][j] = fmaf(a[i], bb[j], acc[i][j]);
        }
        if (has_next) {
            int nxt = cur ^ 1;
            As[nxt][akq + 0][am0] = a_r0.x; As[nxt][akq + 1][am0] = a_r0.y;
            As[nxt][akq + 2][am0] = a_r0.z; As[nxt][akq + 3][am0] = a_r0.w;
            As[nxt][akq + 0][am0 + 64] = a_r1.x; As[nxt][akq + 1][am0 + 64] = a_r1.y;
            As[nxt][akq + 2][am0 + 64] = a_r1.z; As[nxt][akq + 3][am0 + 64] = a_r1.w;
            Ws[nxt][wkq + 0][wn] = w_r.x; Ws[nxt][wkq + 1][wn] = w_r.y;
            Ws[nxt][wkq + 2][wn] = w_r.z; Ws[nxt][wkq + 3][wn] = w_r.w;
            __syncthreads();
            cur = nxt;
        }
    }

#pragma unroll
    for (int i = 0; i < 8; i++) {
        int m = m0 + ty * 8 + i;
        int n = n0 + tx * 4;
        float4 o;
        o.x = acc[i][0] + bias[n + 0];
        o.y = acc[i][1] + bias[n + 1];
        o.z = acc[i][2] + bias[n + 2];
        o.w = acc[i][3] + bias[n + 3];
        *(float4*)&C[(size_t)m * N + n] = o;
    }
}

// ---------------------------------------------------------------------------
// Poison-clear an h buffer before its recurrence launch (graph-replay safe)
// ---------------------------------------------------------------------------
__global__ void clear_nan_kernel(float* __restrict__ buf)
{
    uint4* p = (uint4*)buf;
    const int n4 = LQ * HIDQ / 4;             // 262144 uint4
    uint4 z = make_uint4(NANP, NANP, NANP, NANP);
    for (int i = blockIdx.x * 256 + threadIdx.x; i < n4; i += gridDim.x * 256)
        p[i] = z;
}

// ---------------------------------------------------------------------------
// Persistent bidirectional LSTM layer, register-resident Whh slice.
// Self-tagged values: the h buffer is NaN-poisoned; producers volatile-store
// the h value, consumers poll the VALUE (non-NaN => ready). The poll load IS
// the data load: one L2 round trip, no flags, no fences. Scalar volatile
// polling only (the container-safe class proven in R1/R3/R6/R7/R9).
// ---------------------------------------------------------------------------
__global__ void __launch_bounds__(256, 1)
lstm_layer_kernel(const float* __restrict__ Whh,   // [2][2048][512]
                  const float* __restrict__ xp,    // [2][L][2048] (bias folded in)
                  float* __restrict__ hout)        // [L][1024], NaN-poisoned
{
    __shared__ float h_s[8][64];        // per-warp h chunk staging
    __shared__ float part[2][8][32];    // per-warp partial sums (parity)
    __shared__ float xp_s[2][32];       // xp for 32 rows (parity)

    const int tid  = threadIdx.x;
    const int wid  = tid >> 5;
    const int lane = tid & 31;
    const int b    = blockIdx.x;
    const int d    = b >> 6;
    const int cb   = b & 63;
    const int j0   = cb * JV;

    // --- stage this thread's 64 weights into registers ---
    float4 wr[16];
    {
        const int gate = lane >> 3, jl = lane & 7;
        const float4* src = (const float4*)(Whh +
            ((size_t)d * G4H + (size_t)gate * HDIRQ + j0 + jl) * HDIRQ + wid * 64);
#pragma unroll
        for (int i = 0; i < 16; i++) wr[i] = src[i];
    }

    float c_state = 0.f;                               // lanes 0..7 of warp 0

    for (int step = 0; step < LQ; step++) {
        const int t = (d == 0) ? step : (LQ - 1 - step);
        const int p = step & 1;

        // prefetch xp (warp 1), issued before the poll so latency overlaps
        float xpv = 0.f;
        if (wid == 1) {
            const int gate = lane >> 3, jl = lane & 7;
            xpv = __ldg(xp + ((size_t)d * LQ + t) * G4H +
                        (size_t)gate * HDIRQ + j0 + jl);
        }

        float acc0 = 0.f, acc1 = 0.f, acc2 = 0.f, acc3 = 0.f;
        if (step > 0) {
            const int tp = (d == 0) ? (t - 1) : (t + 1);
            // lane owns chunk-local h indices 2*lane, 2*lane+1
            const float* hp = hout + (size_t)tp * HIDQ + d * HDIRQ +
                              (wid << 6) + (lane << 1);
            unsigned u0, u1;
            int miss = 0;
            for (;;) {
                asm volatile("ld.volatile.global.u32 %0, [%1];"
                             : "=r"(u0) : "l"(hp));
                asm volatile("ld.volatile.global.u32 %0, [%1];"
                             : "=r"(u1) : "l"(hp + 1));
                bool ok = (u0 != NANP) && (u1 != NANP);
                if (__all_sync(0xffffffffu, ok)) break;
                if (++miss > 256) { __nanosleep(128); miss = 0; }
            }
            ((float2*)h_s[wid])[lane] =
                make_float2(__uint_as_float(u0), __uint_as_float(u1));
            __syncwarp();
            const float4* hs4 = (const float4*)h_s[wid];
#pragma unroll
            for (int i = 0; i < 4; i++) {
                float4 h0 = hs4[4 * i + 0], h1 = hs4[4 * i + 1];
                float4 h2 = hs4[4 * i + 2], h3 = hs4[4 * i + 3];
                float4 w0 = wr[4 * i + 0], w1 = wr[4 * i + 1];
                float4 w2 = wr[4 * i + 2], w3 = wr[4 * i + 3];
                acc0 = fmaf(w0.x, h0.x, acc0); acc0 = fmaf(w0.y, h0.y, acc0);
                acc0 = fmaf(w0.z, h0.z, acc0); acc0 = fmaf(w0.w, h0.w, acc0);
                acc1 = fmaf(w1.x, h1.x, acc1); acc1 = fmaf(w1.y, h1.y, acc1);
                acc1 = fmaf(w1.z, h1.z, acc1); acc1 = fmaf(w1.w, h1.w, acc1);
                acc2 = fmaf(w2.x, h2.x, acc2); acc2 = fmaf(w2.y, h2.y, acc2);
                acc2 = fmaf(w2.z, h2.z, acc2); acc2 = fmaf(w2.w, h2.w, acc2);
                acc3 = fmaf(w3.x, h3.x, acc3); acc3 = fmaf(w3.y, h3.y, acc3);
                acc3 = fmaf(w3.z, h3.z, acc3); acc3 = fmaf(w3.w, h3.w, acc3);
            }
        }

        if (wid == 1) xp_s[p][lane] = xpv;
        part[p][wid][lane] = (acc0 + acc1) + (acc2 + acc3);
        __syncthreads();

        if (wid == 0) {
            float tot = 0.f;
#pragma unroll
            for (int w = 0; w < 8; w++) tot += part[p][w][lane];
            const int jj = lane & 7;
            float gi = __shfl_sync(0xffffffffu, tot, jj)      + xp_s[p][jj];
            float gf = __shfl_sync(0xffffffffu, tot, jj + 8)  + xp_s[p][8 + jj];
            float gg = __shfl_sync(0xffffffffu, tot, jj + 16) + xp_s[p][16 + jj];
            float go = __shfl_sync(0xffffffffu, tot, jj + 24) + xp_s[p][24 + jj];
            if (lane < 8) {
                float iv = fast_sigmoid(gi);
                float fv = fast_sigmoid(gf);
                float gv = fast_tanh(gg);
                float ov = fast_sigmoid(go);
                c_state = fv * c_state + iv * gv;
                float hv = ov * fast_tanh(c_state);
                // publish: the value IS the ready signal (finite != NANP)
                float* dst = hout + (size_t)t * HIDQ + d * HDIRQ + j0 + lane;
                asm volatile("st.volatile.global.f32 [%0], %1;"
                             :: "l"(dst), "f"(hv) : "memory");
            }
        }
    }
}

// ---------------------------------------------------------------------------
// s[l] = sum_n tanh(feat[l][n]) * wo[off + n]
// ---------------------------------------------------------------------------
__global__ void reduce_s_kernel(const float* __restrict__ feat, const float* __restrict__ wo,
                                int off, float* __restrict__ s)
{
    int l = blockIdx.x;
    int tid = threadIdx.x;
    float p = 0.f;
    for (int n = tid; n < MLPH; n += 256)
        p += tanhf(feat[(size_t)l * MLPH + n]) * wo[off + n];
    __shared__ float red[8];
#pragma unroll
    for (int o = 16; o > 0; o >>= 1) p += __shfl_xor_sync(0xffffffffu, p, o);
    if ((tid & 31) == 0) red[tid >> 5] = p;
    __syncthreads();
    if (tid < 8) {
        float v = red[tid];
#pragma unroll
        for (int o = 4; o > 0; o >>= 1) v += __shfl_xor_sync(0xffu, v, o);
        if (tid == 0) s[l] = v;
    }
}

// ---------------------------------------------------------------------------
// score[m][h] = s_modif[m] + s_head[h] + bo
// ---------------------------------------------------------------------------
__global__ void score_kernel(const float* __restrict__ sh, const float* __restrict__ sm,
                             const float* __restrict__ bo, float* __restrict__ out)
{
    int idx = blockIdx.x * 256 + threadIdx.x;
    int m = idx >> 10;
    int h = idx & 1023;
    out[idx] = sm[m] + sh[h] + bo[0];
}

// ---------------------------------------------------------------------------
// Launch sequence (graph-capturable)
// ---------------------------------------------------------------------------
extern "C" void kernel_launch(void* const* d_in, const int* in_sizes, int n_in,
                              void* d_out, int out_size)
{
    (void)in_sizes; (void)n_in; (void)out_size;

    const int*   wt   = (const int*)  d_in[0];
    const int*   pt   = (const int*)  d_in[1];
    const float* we   = (const float*)d_in[2];
    const float* pe   = (const float*)d_in[3];
    const float* Wih0 = (const float*)d_in[4];
    const float* Whh0 = (const float*)d_in[5];
    const float* b0   = (const float*)d_in[6];
    const float* Wih1 = (const float*)d_in[7];
    const float* Whh1 = (const float*)d_in[8];
    const float* b1   = (const float*)d_in[9];
    const float* Wh   = (const float*)d_in[10];
    const float* bh   = (const float*)d_in[11];
    const float* Wm   = (const float*)d_in[12];
    const float* bm   = (const float*)d_in[13];
    const float* wo   = (const float*)d_in[14];
    const float* bo   = (const float*)d_in[15];
    float*       out  = (float*)d_out;

    float *p_emb, *p_xp, *p_h0, *p_h1, *p_fH, *p_fM, *p_sh, *p_sm;
    cudaGetSymbolAddress((void**)&p_emb, g_emb);
    cudaGetSymbolAddress((void**)&p_xp,  g_xp);
    cudaGetSymbolAddress((void**)&p_h0,  g_h0);
    cudaGetSymbolAddress((void**)&p_h1,  g_h1);
    cudaGetSymbolAddress((void**)&p_fH,  g_featH);
    cudaGetSymbolAddress((void**)&p_fM,  g_featM);
    cudaGetSymbolAddress((void**)&p_sh,  g_shead);
    cudaGetSymbolAddress((void**)&p_sm,  g_smodif);

    // 1) embeddings
    embed_kernel<<<LQ, 128>>>(wt, pt, we, pe);

    // 2) layer-0 input projections
    {
        dim3 g(G4H / BN, LQ / BM, 2);
        sgemm_bias_kernel<<<g, 256>>>(p_emb, Wih0, b0, p_xp,
                                      LQ, G4H, DIN0,
                                      0LL, (long long)G4H * DIN0, (long long)G4H,
                                      (long long)LQ * G4H);
    }

    // 3) layer-0 recurrence
    clear_nan_kernel<<<512, 256>>>(p_h0);
    lstm_layer_kernel<<<2 * NCTA_DIR, 256>>>(Whh0, p_xp, p_h0);

    // 4) layer-1 input projections (reads layer-0 h buffer directly)
    {
        dim3 g(G4H / BN, LQ / BM, 2);
        sgemm_bias_kernel<<<g, 256>>>(p_h0, Wih1, b1, p_xp,
                                      LQ, G4H, HIDQ,
                                      0LL, (long long)G4H * HIDQ, (long long)G4H,
                                      (long long)LQ * G4H);
    }

    // 5) layer-1 recurrence
    clear_nan_kernel<<<512, 256>>>(p_h1);
    lstm_layer_kernel<<<2 * NCTA_DIR, 256>>>(Whh1, p_xp, p_h1);

    // 6) MLP head features
    {
        dim3 g(MLPH / BN, LQ / BM, 1);
        sgemm_bias_kernel<<<g, 256>>>(p_h1, Wh, bh, p_fH, LQ, MLPH, HIDQ, 0LL, 0LL, 0LL, 0LL);
        sgemm_bias_kernel<<<g, 256>>>(p_h1, Wm, bm, p_fM, LQ, MLPH, HIDQ, 0LL, 0LL, 0LL, 0LL);
    }

    // 7) tanh-dot reductions
    reduce_s_kernel<<<LQ, 256>>>(p_fH, wo, 0,    p_sh);
    reduce_s_kernel<<<LQ, 256>>>(p_fM, wo, MLPH, p_sm);

    // 8) broadcast score matrix
    score_kernel<<<(LQ * LQ) / 256, 256>>>(p_sh, p_sm, bo, out);
}